// round 14
// baseline (speedup 1.0000x reference)
#include <cuda_runtime.h>
#include <cuda_bf16.h>
#include <cuda_fp16.h>
#include <cstdint>

#define Bsz 2048
#define Lsz 512
#define Esz 64
#define Hsz 128
#define Dsz 256
#define Vsz 1000
#define X0W 320

#define SMEM_SWIZZLE_128B(off) ((off) ^ (((off) >> 3) & 0x70))

__device__ __forceinline__ uint32_t smem_to_u32(const void* p) {
    uint32_t a;
    asm("{ .reg .u64 t; cvta.to.shared.u64 t, %1; cvt.u32.u64 %0, t; }"
        : "=r"(a) : "l"(p));
    return a;
}
__device__ __forceinline__ void ldmat4(uint32_t* r, uint32_t addr) {
    asm volatile("ldmatrix.sync.aligned.m8n8.x4.shared.b16 {%0,%1,%2,%3}, [%4];"
                 : "=r"(r[0]), "=r"(r[1]), "=r"(r[2]), "=r"(r[3]) : "r"(addr));
}
__device__ __forceinline__ void mma_f16(float* d, const uint32_t* a, uint32_t b0, uint32_t b1) {
    asm volatile("mma.sync.aligned.m16n8k16.row.col.f32.f16.f16.f32 "
                 "{%0,%1,%2,%3}, {%4,%5,%6,%7}, {%8,%9}, {%0,%1,%2,%3};"
                 : "+f"(d[0]), "+f"(d[1]), "+f"(d[2]), "+f"(d[3])
                 : "r"(a[0]), "r"(a[1]), "r"(a[2]), "r"(a[3]), "r"(b0), "r"(b1));
}
__device__ __forceinline__ void mma_bf16(float* d, const uint32_t* a, uint32_t b0, uint32_t b1) {
    asm volatile("mma.sync.aligned.m16n8k16.row.col.f32.bf16.bf16.f32 "
                 "{%0,%1,%2,%3}, {%4,%5,%6,%7}, {%8,%9}, {%0,%1,%2,%3};"
                 : "+f"(d[0]), "+f"(d[1]), "+f"(d[2]), "+f"(d[3])
                 : "r"(a[0]), "r"(a[1]), "r"(a[2]), "r"(a[3]), "r"(b0), "r"(b1));
}
__device__ __forceinline__ void cp_async16(uint32_t saddr, const void* gaddr) {
    asm volatile("cp.async.ca.shared.global [%0], [%1], 16;" :: "r"(saddr), "l"(gaddr));
}
#define CP_ASYNC_COMMIT() asm volatile("cp.async.commit_group;" ::: "memory")
#define CP_ASYNC_WAIT0()  asm volatile("cp.async.wait_group 0;"  ::: "memory")

__device__ __forceinline__ float tanh_hw(float x) {
    float r;
    asm("tanh.approx.f32 %0, %1;" : "=f"(r) : "f"(x));
    return r;
}

// ===========================================================================
// Scratch
// ===========================================================================
__device__ float g_qproj[Bsz * Hsz];
__device__ float g_x0[Bsz * X0W];
__device__ float g_gi[Bsz * 3 * Hsz];
__device__ float g_gh[Bsz * 3 * Hsz];
__device__ float g_gh2[Bsz * 3 * Hsz];
__device__ __half g_wkH[Hsz * Dsz];
__device__ __nv_bfloat16 g_wqH[Hsz * Hsz],       g_wqL[Hsz * Hsz];
__device__ __nv_bfloat16 g_wih0H[384 * X0W],     g_wih0L[384 * X0W];
__device__ __nv_bfloat16 g_whh0H[384 * Hsz],     g_whh0L[384 * Hsz];
__device__ __nv_bfloat16 g_wih1H[384 * Hsz],     g_wih1L[384 * Hsz];
__device__ __nv_bfloat16 g_whh1H[384 * Hsz],     g_whh1L[384 * Hsz];
__device__ __nv_bfloat16 g_woutH[1024 * Hsz],    g_woutL[1024 * Hsz];

// ---------------------------------------------------------------------------
__device__ __forceinline__ void bf_split(float w, __nv_bfloat16* H, __nv_bfloat16* L, int j) {
    __nv_bfloat16 hi = __float2bfloat16(w);
    H[j] = hi;
    L[j] = __float2bfloat16(w - __bfloat162float(hi));
}

#define O1 16384
#define O2 139264
#define O3 188416
#define O4 237568
#define O5 286720
#define O6 414720
#define O7 447488
#define OT 578560

__global__ void prep_kernel(
    const float* __restrict__ wq,   const float* __restrict__ wih0,
    const float* __restrict__ whh0, const float* __restrict__ wih1,
    const float* __restrict__ whh1, const float* __restrict__ wout,
    const float* __restrict__ wk,   const float* __restrict__ embed)
{
    int i = blockIdx.x * blockDim.x + threadIdx.x;
    if (i >= OT) return;
    if (i < O1)      bf_split(wq[i],        g_wqH,   g_wqL,   i);
    else if (i < O2) { int j = i - O1; bf_split(wih0[j], g_wih0H, g_wih0L, j); }
    else if (i < O3) { int j = i - O2; bf_split(whh0[j], g_whh0H, g_whh0L, j); }
    else if (i < O4) { int j = i - O3; bf_split(wih1[j], g_wih1H, g_wih1L, j); }
    else if (i < O5) { int j = i - O4; bf_split(whh1[j], g_whh1H, g_whh1L, j); }
    else if (i < O6) { int j = i - O5; bf_split(wout[j], g_woutH, g_woutL, j); }
    else if (i < O7) { int j = i - O6; g_wkH[j] = __float2half_rn(wk[j]); }
    else             { int j = i - O7; int b = j >> 6, e = j & 63;
                       g_x0[b * X0W + e] = embed[b * 64 + e]; }
}

// ===========================================================================
// 64x128-tile batched GEMM (3-term bf16 split), blockIdx.z selects job.
// 8 warps as 2(m:32) x 4(n:32).
// ===========================================================================
struct GJob {
    const float* A;
    const __nv_bfloat16* wH;
    const __nv_bfloat16* wL;
    const float* bias;
    float* C;
    int lda;
    int nChunks;
    int N;
};

#define G_SA_HI 0
#define G_SA_LO 8192
#define G_SB_HI 16384
#define G_SB_LO 32768
#define G_SMEM  49152

__global__ __launch_bounds__(256, 2) void mma_gemm64_kernel(GJob j0, GJob j1, GJob j2)
{
    GJob j = (blockIdx.z == 0) ? j0 : (blockIdx.z == 1 ? j1 : j2);
    extern __shared__ char smem[];
    uint32_t sbase = smem_to_u32(smem);
    int t    = threadIdx.x;
    int lane = t & 31, w = t >> 5;
    int wr   = w & 1,  wc = w >> 1;
    int m0   = blockIdx.y * 64;
    int n0   = blockIdx.x * 128;

    float acc[2][4][4];
    #pragma unroll
    for (int mt = 0; mt < 2; mt++)
        #pragma unroll
        for (int nt = 0; nt < 4; nt++)
            #pragma unroll
            for (int i = 0; i < 4; i++) acc[mt][nt][i] = 0.f;

    for (int c = 0; c < j.nChunks; c++) {
        int d0 = c * 64;
        // ---- W chunk (128 rows x 64 cols) hi/lo via cp.async ----
        #pragma unroll
        for (int i = 0; i < 4; i++) {
            int idx = t + i * 256;           // 16B units, 8 per row
            int row = idx >> 3;
            int u   = idx & 7;
            uint32_t off = SMEM_SWIZZLE_128B((uint32_t)(row * 128 + u * 16));
            cp_async16(sbase + G_SB_HI + off, j.wH + (size_t)(n0 + row) * j.lda + d0 + u * 8);
            cp_async16(sbase + G_SB_LO + off, j.wL + (size_t)(n0 + row) * j.lda + d0 + u * 8);
        }
        CP_ASYNC_COMMIT();
        // ---- A chunk (64 rows x 64 cols): fp32 -> bf16 hi/lo ----
        #pragma unroll
        for (int i = 0; i < 4; i++) {
            int idx = t + i * 256;           // float4 units, 16 per row
            int row = idx >> 4;
            int dq  = idx & 15;
            float4 v4 = *(const float4*)(j.A + (size_t)(m0 + row) * j.lda + d0 + dq * 4);
            __nv_bfloat16 h0 = __float2bfloat16(v4.x);
            __nv_bfloat16 h1 = __float2bfloat16(v4.y);
            __nv_bfloat16 h2 = __float2bfloat16(v4.z);
            __nv_bfloat16 h3 = __float2bfloat16(v4.w);
            __nv_bfloat16 r0 = __float2bfloat16(v4.x - __bfloat162float(h0));
            __nv_bfloat16 r1 = __float2bfloat16(v4.y - __bfloat162float(h1));
            __nv_bfloat16 r2 = __float2bfloat16(v4.z - __bfloat162float(h2));
            __nv_bfloat16 r3 = __float2bfloat16(v4.w - __bfloat162float(h3));
            uint32_t off = SMEM_SWIZZLE_128B((uint32_t)(row * 128 + dq * 8));
            uint2 hv, lv;
            hv.x = (uint32_t)__bfloat16_as_ushort(h0) | ((uint32_t)__bfloat16_as_ushort(h1) << 16);
            hv.y = (uint32_t)__bfloat16_as_ushort(h2) | ((uint32_t)__bfloat16_as_ushort(h3) << 16);
            lv.x = (uint32_t)__bfloat16_as_ushort(r0) | ((uint32_t)__bfloat16_as_ushort(r1) << 16);
            lv.y = (uint32_t)__bfloat16_as_ushort(r2) | ((uint32_t)__bfloat16_as_ushort(r3) << 16);
            *(uint2*)(smem + G_SA_HI + off) = hv;
            *(uint2*)(smem + G_SA_LO + off) = lv;
        }
        CP_ASYNC_WAIT0();
        __syncthreads();

        #pragma unroll
        for (int ks = 0; ks < 4; ks++) {
            int kb = ks * 32;
            uint32_t ah[2][4], al[2][4];
            #pragma unroll
            for (int mt = 0; mt < 2; mt++) {
                int row  = wr * 32 + mt * 16 + (lane & 15);
                int colb = kb + (lane >> 4) * 16;
                uint32_t off = SMEM_SWIZZLE_128B((uint32_t)(row * 128 + colb));
                ldmat4(ah[mt], sbase + G_SA_HI + off);
                ldmat4(al[mt], sbase + G_SA_LO + off);
            }
            #pragma unroll
            for (int p = 0; p < 2; p++) {
                int row  = wc * 32 + p * 16 + (lane & 15);
                int colb = kb + (lane >> 4) * 16;
                uint32_t off = SMEM_SWIZZLE_128B((uint32_t)(row * 128 + colb));
                uint32_t rh[4], rl[4];
                ldmat4(rh, sbase + G_SB_HI + off);
                ldmat4(rl, sbase + G_SB_LO + off);
                #pragma unroll
                for (int mt = 0; mt < 2; mt++) {
                    mma_bf16(acc[mt][p*2],   ah[mt], rh[0], rh[2]);
                    mma_bf16(acc[mt][p*2+1], ah[mt], rh[1], rh[3]);
                    mma_bf16(acc[mt][p*2],   al[mt], rh[0], rh[2]);
                    mma_bf16(acc[mt][p*2+1], al[mt], rh[1], rh[3]);
                    mma_bf16(acc[mt][p*2],   ah[mt], rl[0], rl[2]);
                    mma_bf16(acc[mt][p*2+1], ah[mt], rl[1], rl[3]);
                }
            }
        }
        __syncthreads();
    }

    #pragma unroll
    for (int mt = 0; mt < 2; mt++)
        #pragma unroll
        for (int nt = 0; nt < 4; nt++)
            #pragma unroll
            for (int i = 0; i < 4; i++) {
                int row = m0 + wr * 32 + mt * 16 + (lane >> 2) + (i >= 2 ? 8 : 0);
                int col = n0 + wc * 32 + nt * 8 + (lane & 3) * 2 + (i & 1);
                if (col < j.N) {
                    float v = acc[mt][nt][i];
                    if (j.bias) v += j.bias[col];
                    j.C[(size_t)row * j.N + col] = v;
                }
            }
}

// ===========================================================================
// FUSED attention: Wk fragments hoisted to registers (one-time 2-pass
// extraction), 16 tiles x 32 l-rows, double-buffered SA, pf prefetch.
// ===========================================================================
#define SA_OFF 0                 // 2 x 16KB buffers
#define FS_SMEM 32768

__global__ __launch_bounds__(256, 2) void fused_attn_kernel(
    const float* __restrict__ enc, const float* __restrict__ attn_v,
    float* __restrict__ attnw_out, float* __restrict__ x0_out)
{
    extern __shared__ char smem[];
    __shared__ float qs[128], vs[128];
    __shared__ float sred[8][32];
    __shared__ float e_all[Lsz];
    __shared__ float e_w[32];
    __shared__ float sm_invZ;

    uint32_t sbase = smem_to_u32(smem);
    int t    = threadIdx.x;
    int lane = t & 31, w = t >> 5;
    int b    = blockIdx.x;

    if (t < 128) { qs[t] = g_qproj[b * Hsz + t]; vs[t] = attn_v[t]; }

    const float* encb = enc + (size_t)b * Lsz * Dsz;
    int s_row = t >> 5;
    int s_cu  = t & 31;

    // ---- prefetch tile 0 (half: 2 units = 16 regs), hides behind Wk setup ----
    float4 pf[4];
    #pragma unroll
    for (int i = 0; i < 2; i++) {
        const float* src = encb + (size_t)(s_row + i * 8) * Dsz + s_cu * 8;
        pf[i * 2]     = *(const float4*)(src);
        pf[i * 2 + 1] = *(const float4*)(src + 4);
    }

    // ---- Wk -> register fragments, 2 passes of 64 rows through SA ----
    uint32_t bfr[16][4];            // 64 regs: B frags for all 16 k-steps
    #pragma unroll
    for (int pass = 0; pass < 2; pass++) {
        // stage rows [pass*64, pass*64+64) into SA (32KB)
        #pragma unroll
        for (int i = 0; i < 8; i++) {
            int u   = t + i * 256;          // 16B units, 32 per row
            int row = u >> 5;
            int cu  = u & 31;
            uint32_t dst = sbase + SA_OFF + (uint32_t)(row * 512 + ((cu ^ (row & 7)) << 4));
            cp_async16(dst, g_wkH + (size_t)(pass * 64 + row) * Dsz + cu * 8);
        }
        CP_ASYNC_COMMIT();
        CP_ASYNC_WAIT0();
        __syncthreads();
        if ((w >> 2) == pass) {             // warps 0-3 in pass 0, 4-7 in pass 1
            int brow = (w * 16 - pass * 64) + (lane & 15);
            #pragma unroll
            for (int ks = 0; ks < 16; ks++) {
                int cuk = ks * 2 + (lane >> 4);
                uint32_t off = (uint32_t)(brow * 512 + ((cuk ^ (brow & 7)) << 4));
                ldmat4(bfr[ks], sbase + SA_OFF + off);
            }
        }
        __syncthreads();
    }

    float2 ctx = make_float2(0.f, 0.f);
    float Zloc = 0.f;

    for (int tile = 0; tile < 16; tile++) {
        uint32_t bufo = SA_OFF + (uint32_t)((tile & 1) << 14);
        // ---- stage: 2 units from pf, 2 units direct ----
        #pragma unroll
        for (int i = 0; i < 2; i++) {
            int row = s_row + i * 8;
            __half2 h0 = __floats2half2_rn(pf[i*2].x,   pf[i*2].y);
            __half2 h1 = __floats2half2_rn(pf[i*2].z,   pf[i*2].w);
            __half2 h2 = __floats2half2_rn(pf[i*2+1].x, pf[i*2+1].y);
            __half2 h3 = __floats2half2_rn(pf[i*2+1].z, pf[i*2+1].w);
            uint4 pk;
            pk.x = *(uint32_t*)&h0; pk.y = *(uint32_t*)&h1;
            pk.z = *(uint32_t*)&h2; pk.w = *(uint32_t*)&h3;
            uint32_t off = (uint32_t)(row * 512 + ((s_cu ^ (row & 7)) << 4));
            *(uint4*)(smem + bufo + off) = pk;
        }
        #pragma unroll
        for (int i = 2; i < 4; i++) {
            int row = s_row + i * 8;
            const float* src = encb + (size_t)(tile * 32 + row) * Dsz + s_cu * 8;
            float4 v0 = *(const float4*)(src);
            float4 v1 = *(const float4*)(src + 4);
            __half2 h0 = __floats2half2_rn(v0.x, v0.y);
            __half2 h1 = __floats2half2_rn(v0.z, v0.w);
            __half2 h2 = __floats2half2_rn(v1.x, v1.y);
            __half2 h3 = __floats2half2_rn(v1.z, v1.w);
            uint4 pk;
            pk.x = *(uint32_t*)&h0; pk.y = *(uint32_t*)&h1;
            pk.z = *(uint32_t*)&h2; pk.w = *(uint32_t*)&h3;
            uint32_t off = (uint32_t)(row * 512 + ((s_cu ^ (row & 7)) << 4));
            *(uint4*)(smem + bufo + off) = pk;
        }
        __syncthreads();                                    // S1

        // ---- prefetch next tile (half) ----
        if (tile < 15) {
            const float* nb = encb + (size_t)((tile + 1) * 32) * Dsz;
            #pragma unroll
            for (int i = 0; i < 2; i++) {
                const float* src = nb + (size_t)(s_row + i * 8) * Dsz + s_cu * 8;
                pf[i * 2]     = *(const float4*)(src);
                pf[i * 2 + 1] = *(const float4*)(src + 4);
            }
        }

        // ---- MMA: 32l x 128h, K=256; B from registers ----
        float acc[2][2][4];
        #pragma unroll
        for (int mt = 0; mt < 2; mt++)
            #pragma unroll
            for (int nt = 0; nt < 2; nt++)
                #pragma unroll
                for (int i = 0; i < 4; i++) acc[mt][nt][i] = 0.f;

        #pragma unroll
        for (int ks = 0; ks < 16; ks++) {
            int cuk = ks * 2 + (lane >> 4);
            uint32_t ah[2][4];
            #pragma unroll
            for (int mt = 0; mt < 2; mt++) {
                int row = mt * 16 + (lane & 15);
                uint32_t off = (uint32_t)(row * 512 + ((cuk ^ (row & 7)) << 4));
                ldmat4(ah[mt], sbase + bufo + off);
            }
            #pragma unroll
            for (int mt = 0; mt < 2; mt++) {
                mma_f16(acc[mt][0], ah[mt], bfr[ks][0], bfr[ks][2]);
                mma_f16(acc[mt][1], ah[mt], bfr[ks][1], bfr[ks][3]);
            }
        }

        // ---- epilogue ----
        float part[4];
        #pragma unroll
        for (int mt = 0; mt < 2; mt++)
            #pragma unroll
            for (int half = 0; half < 2; half++) {
                float p = 0.f;
                #pragma unroll
                for (int nt = 0; nt < 2; nt++)
                    #pragma unroll
                    for (int j = 0; j < 2; j++) {
                        int h = w * 16 + nt * 8 + (lane & 3) * 2 + j;
                        float e = acc[mt][nt][half * 2 + j] + qs[h];
                        p += vs[h] * tanh_hw(e);
                    }
                part[mt * 2 + half] = p;
            }
        #pragma unroll
        for (int k = 0; k < 4; k++) {
            part[k] += __shfl_xor_sync(0xffffffffu, part[k], 1);
            part[k] += __shfl_xor_sync(0xffffffffu, part[k], 2);
        }
        if ((lane & 3) == 0) {
            #pragma unroll
            for (int mt = 0; mt < 2; mt++)
                #pragma unroll
                for (int half = 0; half < 2; half++) {
                    int row = mt * 16 + half * 8 + (lane >> 2);
                    sred[w][row] = part[mt * 2 + half];
                }
        }
        __syncthreads();                                    // S2

        if (t < 32) {
            float s = sred[0][t] + sred[1][t] + sred[2][t] + sred[3][t]
                    + sred[4][t] + sred[5][t] + sred[6][t] + sred[7][t];
            float e = __expf(s);
            e_w[t] = e;
            e_all[tile * 32 + t] = e;
            Zloc += e;
        }
        __syncthreads();                                    // S3

        if (t < 128) {
            int cu = t >> 2, byo = (4 * t) & 15;
            float2 cacc = make_float2(0.f, 0.f);
            #pragma unroll 8
            for (int l = 0; l < 32; l++) {
                uint32_t off = (uint32_t)(l * 512 + ((cu ^ (l & 7)) << 4) + byo);
                __half2 hv = *(const __half2*)(smem + bufo + off);
                float2 fv = __half22float2(hv);
                float e = e_w[l];
                cacc.x += e * fv.x;
                cacc.y += e * fv.y;
            }
            ctx.x += cacc.x;
            ctx.y += cacc.y;
        }
    }

    __syncthreads();
    if (t < 32) {
        float z = Zloc;
        #pragma unroll
        for (int o = 16; o > 0; o >>= 1)
            z += __shfl_xor_sync(0xffffffffu, z, o);
        if (lane == 0) sm_invZ = 1.f / z;
    }
    __syncthreads();

    float invZ = sm_invZ;
    if (t < 128) {
        x0_out[(size_t)b * X0W + Esz + 2 * t]     = ctx.x * invZ;
        x0_out[(size_t)b * X0W + Esz + 2 * t + 1] = ctx.y * invZ;
    }
    attnw_out[(size_t)b * Lsz + t]       = e_all[t]       * invZ;
    attnw_out[(size_t)b * Lsz + t + 256] = e_all[t + 256] * invZ;
}

// ---------------------------------------------------------------------------
__global__ void gru_kernel(const float* __restrict__ hprev, float* __restrict__ hnew,
                           const float* __restrict__ gi, const float* __restrict__ gh) {
    int b = blockIdx.x, h = threadIdx.x;
    int base = b * 3 * Hsz;
    float r = 1.f / (1.f + __expf(-(gi[base + h]       + gh[base + h])));
    float z = 1.f / (1.f + __expf(-(gi[base + Hsz + h] + gh[base + Hsz + h])));
    float n = tanhf(gi[base + 2 * Hsz + h] + r * gh[base + 2 * Hsz + h]);
    hnew[b * Hsz + h] = (1.f - z) * n + z * hprev[b * Hsz + h];
}

// ===========================================================================
extern "C" void kernel_launch(void* const* d_in, const int* in_sizes, int n_in,
                              void* d_out, int out_size)
{
    const float* embed  = (const float*)d_in[0];
    const float* hidden = (const float*)d_in[1];
    const float* enc    = (const float*)d_in[2];
    const float* Wq     = (const float*)d_in[3];
    const float* Wk     = (const float*)d_in[4];
    const float* av     = (const float*)d_in[5];
    const float* Wih0   = (const float*)d_in[6];
    const float* Whh0   = (const float*)d_in[7];
    const float* bih0   = (const float*)d_in[8];
    const float* bhh0   = (const float*)d_in[9];
    const float* Wih1   = (const float*)d_in[10];
    const float* Whh1   = (const float*)d_in[11];
    const float* bih1   = (const float*)d_in[12];
    const float* bhh1   = (const float*)d_in[13];
    const float* Wout   = (const float*)d_in[14];
    const float* bout   = (const float*)d_in[15];

    float* out_logits = (float*)d_out;
    float* out_hidden = out_logits + (size_t)Bsz * Vsz;
    float* out_attnw  = out_hidden + (size_t)2 * Bsz * Hsz;

    float *p_qproj, *p_x0, *p_gi, *p_gh, *p_gh2;
    cudaGetSymbolAddress((void**)&p_qproj, g_qproj);
    cudaGetSymbolAddress((void**)&p_x0,    g_x0);
    cudaGetSymbolAddress((void**)&p_gi,    g_gi);
    cudaGetSymbolAddress((void**)&p_gh,    g_gh);
    cudaGetSymbolAddress((void**)&p_gh2,   g_gh2);

    __nv_bfloat16 *wqH, *wqL, *wih0H, *wih0L, *whh0H, *whh0L,
                  *wih1H, *wih1L, *whh1H, *whh1L, *woutH, *woutL;
    cudaGetSymbolAddress((void**)&wqH,   g_wqH);   cudaGetSymbolAddress((void**)&wqL,   g_wqL);
    cudaGetSymbolAddress((void**)&wih0H, g_wih0H); cudaGetSymbolAddress((void**)&wih0L, g_wih0L);
    cudaGetSymbolAddress((void**)&whh0H, g_whh0H); cudaGetSymbolAddress((void**)&whh0L, g_whh0L);
    cudaGetSymbolAddress((void**)&wih1H, g_wih1H); cudaGetSymbolAddress((void**)&wih1L, g_wih1L);
    cudaGetSymbolAddress((void**)&whh1H, g_whh1H); cudaGetSymbolAddress((void**)&whh1L, g_whh1L);
    cudaGetSymbolAddress((void**)&woutH, g_woutH); cudaGetSymbolAddress((void**)&woutL, g_woutL);

    cudaFuncSetAttribute(fused_attn_kernel,
                         cudaFuncAttributeMaxDynamicSharedMemorySize, FS_SMEM);
    cudaFuncSetAttribute(mma_gemm64_kernel,
                         cudaFuncAttributeMaxDynamicSharedMemorySize, G_SMEM);

    const float* h0_prev = hidden;
    const float* h1_prev = hidden + (size_t)Bsz * Hsz;
    float* h0_new = out_hidden;
    float* h1_new = out_hidden + (size_t)Bsz * Hsz;

    // 1) prep
    prep_kernel<<<(OT + 255) / 256, 256>>>(Wq, Wih0, Whh0, Wih1, Whh1, Wout, Wk, embed);

    // 2) qproj = h1 @ Wq^T   (grid 32 blocks)
    GJob jq  = { h1_prev, wqH, wqL, nullptr, p_qproj, Hsz, 2, Hsz };
    mma_gemm64_kernel<<<dim3(1, 32, 1), 256, G_SMEM>>>(jq, jq, jq);

    // 3) fused attention
    fused_attn_kernel<<<Bsz, 256, FS_SMEM>>>(enc, av, out_attnw, p_x0);

    // 4) batched: gi0, gh0, gh1 (all independent; 288 blocks)
    GJob ja = { p_x0,    wih0H, wih0L, bih0, p_gi,  X0W, 5, 384 };
    GJob jb = { h0_prev, whh0H, whh0L, bhh0, p_gh,  Hsz, 2, 384 };
    GJob jc = { h1_prev, whh1H, whh1L, bhh1, p_gh2, Hsz, 2, 384 };
    mma_gemm64_kernel<<<dim3(3, 32, 3), 256, G_SMEM>>>(ja, jb, jc);

    // 5) gru0 -> h0_new
    gru_kernel<<<Bsz, Hsz>>>(h0_prev, h0_new, p_gi, p_gh);

    // 6) gi1 = h0_new @ Wih1^T (96 blocks)
    GJob jd = { h0_new, wih1H, wih1L, bih1, p_gi, Hsz, 2, 384 };
    mma_gemm64_kernel<<<dim3(3, 32, 1), 256, G_SMEM>>>(jd, jd, jd);

    // 7) gru1 -> h1_new (gh from pre-computed gh2)
    gru_kernel<<<Bsz, Hsz>>>(h1_prev, h1_new, p_gi, p_gh2);

    // 8) logits (256 blocks)
    GJob jl = { h1_new, woutH, woutL, bout, out_logits, Hsz, 2, Vsz };
    mma_gemm64_kernel<<<dim3(8, 32, 1), 256, G_SMEM>>>(jl, jl, jl);
}

// round 16
// speedup vs baseline: 1.4050x; 1.4050x over previous
#include <cuda_runtime.h>
#include <cuda_bf16.h>
#include <cuda_fp16.h>
#include <cstdint>

#define Bsz 2048
#define Lsz 512
#define Esz 64
#define Hsz 128
#define Dsz 256
#define Vsz 1000
#define X0W 320

#define SMEM_SWIZZLE_128B(off) ((off) ^ (((off) >> 3) & 0x70))

__device__ __forceinline__ uint32_t smem_to_u32(const void* p) {
    uint32_t a;
    asm("{ .reg .u64 t; cvta.to.shared.u64 t, %1; cvt.u32.u64 %0, t; }"
        : "=r"(a) : "l"(p));
    return a;
}
__device__ __forceinline__ void ldmat4(uint32_t* r, uint32_t addr) {
    asm volatile("ldmatrix.sync.aligned.m8n8.x4.shared.b16 {%0,%1,%2,%3}, [%4];"
                 : "=r"(r[0]), "=r"(r[1]), "=r"(r[2]), "=r"(r[3]) : "r"(addr));
}
__device__ __forceinline__ void mma_f16(float* d, const uint32_t* a, uint32_t b0, uint32_t b1) {
    asm volatile("mma.sync.aligned.m16n8k16.row.col.f32.f16.f16.f32 "
                 "{%0,%1,%2,%3}, {%4,%5,%6,%7}, {%8,%9}, {%0,%1,%2,%3};"
                 : "+f"(d[0]), "+f"(d[1]), "+f"(d[2]), "+f"(d[3])
                 : "r"(a[0]), "r"(a[1]), "r"(a[2]), "r"(a[3]), "r"(b0), "r"(b1));
}
__device__ __forceinline__ void mma_bf16(float* d, const uint32_t* a, uint32_t b0, uint32_t b1) {
    asm volatile("mma.sync.aligned.m16n8k16.row.col.f32.bf16.bf16.f32 "
                 "{%0,%1,%2,%3}, {%4,%5,%6,%7}, {%8,%9}, {%0,%1,%2,%3};"
                 : "+f"(d[0]), "+f"(d[1]), "+f"(d[2]), "+f"(d[3])
                 : "r"(a[0]), "r"(a[1]), "r"(a[2]), "r"(a[3]), "r"(b0), "r"(b1));
}
__device__ __forceinline__ void cp_async16(uint32_t saddr, const void* gaddr) {
    asm volatile("cp.async.ca.shared.global [%0], [%1], 16;" :: "r"(saddr), "l"(gaddr));
}
#define CP_ASYNC_COMMIT() asm volatile("cp.async.commit_group;" ::: "memory")
#define CP_ASYNC_WAIT0()  asm volatile("cp.async.wait_group 0;"  ::: "memory")

__device__ __forceinline__ float tanh_hw(float x) {
    float r;
    asm("tanh.approx.f32 %0, %1;" : "=f"(r) : "f"(x));
    return r;
}

// ===========================================================================
// Scratch
// ===========================================================================
__device__ float g_qproj[Bsz * Hsz];
__device__ float g_x0[Bsz * X0W];
__device__ float g_gi[Bsz * 3 * Hsz];
__device__ float g_gh[Bsz * 3 * Hsz];
__device__ float g_gh2[Bsz * 3 * Hsz];
__device__ __half g_wkH[Hsz * Dsz];
__device__ __nv_bfloat16 g_wqH[Hsz * Hsz],       g_wqL[Hsz * Hsz];
__device__ __nv_bfloat16 g_wih0H[384 * X0W],     g_wih0L[384 * X0W];
__device__ __nv_bfloat16 g_whh0H[384 * Hsz],     g_whh0L[384 * Hsz];
__device__ __nv_bfloat16 g_wih1H[384 * Hsz],     g_wih1L[384 * Hsz];
__device__ __nv_bfloat16 g_whh1H[384 * Hsz],     g_whh1L[384 * Hsz];
__device__ __nv_bfloat16 g_woutH[1024 * Hsz],    g_woutL[1024 * Hsz];

// ---------------------------------------------------------------------------
__device__ __forceinline__ void bf_split(float w, __nv_bfloat16* H, __nv_bfloat16* L, int j) {
    __nv_bfloat16 hi = __float2bfloat16(w);
    H[j] = hi;
    L[j] = __float2bfloat16(w - __bfloat162float(hi));
}

#define O1 16384
#define O2 139264
#define O3 188416
#define O4 237568
#define O5 286720
#define O6 414720
#define O7 447488
#define OT 578560

__global__ void prep_kernel(
    const float* __restrict__ wq,   const float* __restrict__ wih0,
    const float* __restrict__ whh0, const float* __restrict__ wih1,
    const float* __restrict__ whh1, const float* __restrict__ wout,
    const float* __restrict__ wk,   const float* __restrict__ embed)
{
    int i = blockIdx.x * blockDim.x + threadIdx.x;
    if (i >= OT) return;
    if (i < O1)      bf_split(wq[i],        g_wqH,   g_wqL,   i);
    else if (i < O2) { int j = i - O1; bf_split(wih0[j], g_wih0H, g_wih0L, j); }
    else if (i < O3) { int j = i - O2; bf_split(whh0[j], g_whh0H, g_whh0L, j); }
    else if (i < O4) { int j = i - O3; bf_split(wih1[j], g_wih1H, g_wih1L, j); }
    else if (i < O5) { int j = i - O4; bf_split(whh1[j], g_whh1H, g_whh1L, j); }
    else if (i < O6) { int j = i - O5; bf_split(wout[j], g_woutH, g_woutL, j); }
    else if (i < O7) { int j = i - O6; g_wkH[j] = __float2half_rn(wk[j]); }
    else             { int j = i - O7; int b = j >> 6, e = j & 63;
                       g_x0[b * X0W + e] = embed[b * 64 + e]; }
}

// ===========================================================================
// 64x128-tile batched GEMM (3-term bf16 split), blockIdx.z selects job.
// ===========================================================================
struct GJob {
    const float* A;
    const __nv_bfloat16* wH;
    const __nv_bfloat16* wL;
    const float* bias;
    float* C;
    int lda;
    int nChunks;
    int N;
};

#define G_SA_HI 0
#define G_SA_LO 8192
#define G_SB_HI 16384
#define G_SB_LO 32768
#define G_SMEM  49152

__global__ __launch_bounds__(256, 2) void mma_gemm64_kernel(GJob j0, GJob j1, GJob j2)
{
    GJob j = (blockIdx.z == 0) ? j0 : (blockIdx.z == 1 ? j1 : j2);
    extern __shared__ char smem[];
    uint32_t sbase = smem_to_u32(smem);
    int t    = threadIdx.x;
    int lane = t & 31, w = t >> 5;
    int wr   = w & 1,  wc = w >> 1;
    int m0   = blockIdx.y * 64;
    int n0   = blockIdx.x * 128;

    float acc[2][4][4];
    #pragma unroll
    for (int mt = 0; mt < 2; mt++)
        #pragma unroll
        for (int nt = 0; nt < 4; nt++)
            #pragma unroll
            for (int i = 0; i < 4; i++) acc[mt][nt][i] = 0.f;

    for (int c = 0; c < j.nChunks; c++) {
        int d0 = c * 64;
        #pragma unroll
        for (int i = 0; i < 4; i++) {
            int idx = t + i * 256;
            int row = idx >> 3;
            int u   = idx & 7;
            uint32_t off = SMEM_SWIZZLE_128B((uint32_t)(row * 128 + u * 16));
            cp_async16(sbase + G_SB_HI + off, j.wH + (size_t)(n0 + row) * j.lda + d0 + u * 8);
            cp_async16(sbase + G_SB_LO + off, j.wL + (size_t)(n0 + row) * j.lda + d0 + u * 8);
        }
        CP_ASYNC_COMMIT();
        #pragma unroll
        for (int i = 0; i < 4; i++) {
            int idx = t + i * 256;
            int row = idx >> 4;
            int dq  = idx & 15;
            float4 v4 = *(const float4*)(j.A + (size_t)(m0 + row) * j.lda + d0 + dq * 4);
            __nv_bfloat16 h0 = __float2bfloat16(v4.x);
            __nv_bfloat16 h1 = __float2bfloat16(v4.y);
            __nv_bfloat16 h2 = __float2bfloat16(v4.z);
            __nv_bfloat16 h3 = __float2bfloat16(v4.w);
            __nv_bfloat16 r0 = __float2bfloat16(v4.x - __bfloat162float(h0));
            __nv_bfloat16 r1 = __float2bfloat16(v4.y - __bfloat162float(h1));
            __nv_bfloat16 r2 = __float2bfloat16(v4.z - __bfloat162float(h2));
            __nv_bfloat16 r3 = __float2bfloat16(v4.w - __bfloat162float(h3));
            uint32_t off = SMEM_SWIZZLE_128B((uint32_t)(row * 128 + dq * 8));
            uint2 hv, lv;
            hv.x = (uint32_t)__bfloat16_as_ushort(h0) | ((uint32_t)__bfloat16_as_ushort(h1) << 16);
            hv.y = (uint32_t)__bfloat16_as_ushort(h2) | ((uint32_t)__bfloat16_as_ushort(h3) << 16);
            lv.x = (uint32_t)__bfloat16_as_ushort(r0) | ((uint32_t)__bfloat16_as_ushort(r1) << 16);
            lv.y = (uint32_t)__bfloat16_as_ushort(r2) | ((uint32_t)__bfloat16_as_ushort(r3) << 16);
            *(uint2*)(smem + G_SA_HI + off) = hv;
            *(uint2*)(smem + G_SA_LO + off) = lv;
        }
        CP_ASYNC_WAIT0();
        __syncthreads();

        #pragma unroll
        for (int ks = 0; ks < 4; ks++) {
            int kb = ks * 32;
            uint32_t ah[2][4], al[2][4];
            #pragma unroll
            for (int mt = 0; mt < 2; mt++) {
                int row  = wr * 32 + mt * 16 + (lane & 15);
                int colb = kb + (lane >> 4) * 16;
                uint32_t off = SMEM_SWIZZLE_128B((uint32_t)(row * 128 + colb));
                ldmat4(ah[mt], sbase + G_SA_HI + off);
                ldmat4(al[mt], sbase + G_SA_LO + off);
            }
            #pragma unroll
            for (int p = 0; p < 2; p++) {
                int row  = wc * 32 + p * 16 + (lane & 15);
                int colb = kb + (lane >> 4) * 16;
                uint32_t off = SMEM_SWIZZLE_128B((uint32_t)(row * 128 + colb));
                uint32_t rh[4], rl[4];
                ldmat4(rh, sbase + G_SB_HI + off);
                ldmat4(rl, sbase + G_SB_LO + off);
                #pragma unroll
                for (int mt = 0; mt < 2; mt++) {
                    mma_bf16(acc[mt][p*2],   ah[mt], rh[0], rh[2]);
                    mma_bf16(acc[mt][p*2+1], ah[mt], rh[1], rh[3]);
                    mma_bf16(acc[mt][p*2],   al[mt], rh[0], rh[2]);
                    mma_bf16(acc[mt][p*2+1], al[mt], rh[1], rh[3]);
                    mma_bf16(acc[mt][p*2],   ah[mt], rl[0], rl[2]);
                    mma_bf16(acc[mt][p*2+1], ah[mt], rl[1], rl[3]);
                }
            }
        }
        __syncthreads();
    }

    #pragma unroll
    for (int mt = 0; mt < 2; mt++)
        #pragma unroll
        for (int nt = 0; nt < 4; nt++)
            #pragma unroll
            for (int i = 0; i < 4; i++) {
                int row = m0 + wr * 32 + mt * 16 + (lane >> 2) + (i >= 2 ? 8 : 0);
                int col = n0 + wc * 32 + nt * 8 + (lane & 3) * 2 + (i & 1);
                if (col < j.N) {
                    float v = acc[mt][nt][i];
                    if (j.bias) v += j.bias[col];
                    j.C[(size_t)row * j.N + col] = v;
                }
            }
}

// ===========================================================================
// FUSED attention — EXACT R13 version (Wk resident in smem, 16-tile
// double-buffered pipeline, fixed-max softmax).
// ===========================================================================
#define SB_OFF 0                 // Wk fp16 resident: 64KB
#define SA_OFF 65536             // 2 buffers x 16KB
#define FS_SMEM (65536 + 32768)

__global__ __launch_bounds__(256, 2) void fused_attn_kernel(
    const float* __restrict__ enc, const float* __restrict__ attn_v,
    float* __restrict__ attnw_out, float* __restrict__ x0_out)
{
    extern __shared__ char smem[];
    __shared__ float qs[128], vs[128];
    __shared__ float sred[8][32];
    __shared__ float e_all[Lsz];
    __shared__ float e_w[32];
    __shared__ float sm_invZ;

    uint32_t sbase = smem_to_u32(smem);
    int t    = threadIdx.x;
    int lane = t & 31, w = t >> 5;
    int b    = blockIdx.x;

    // ---- preload Wk fp16 (64KB) ----
    #pragma unroll
    for (int i = 0; i < 16; i++) {
        int u   = t + i * 256;
        int row = u >> 5;
        int cu  = u & 31;
        uint32_t dst = sbase + SB_OFF + (uint32_t)(row * 512 + ((cu ^ (row & 7)) << 4));
        cp_async16(dst, g_wkH + (size_t)row * Dsz + cu * 8);
    }
    CP_ASYNC_COMMIT();

    if (t < 128) { qs[t] = g_qproj[b * Hsz + t]; vs[t] = attn_v[t]; }

    const float* encb = enc + (size_t)b * Lsz * Dsz;
    float2 ctx = make_float2(0.f, 0.f);
    float Zloc = 0.f;

    int s_row = t >> 5;
    int s_cu  = t & 31;

    float4 pf[8];
    #pragma unroll
    for (int i = 0; i < 4; i++) {
        const float* src = encb + (size_t)(s_row + i * 8) * Dsz + s_cu * 8;
        pf[i * 2]     = *(const float4*)(src);
        pf[i * 2 + 1] = *(const float4*)(src + 4);
    }

    for (int tile = 0; tile < 16; tile++) {
        uint32_t bufo = SA_OFF + (uint32_t)((tile & 1) << 14);
        #pragma unroll
        for (int i = 0; i < 4; i++) {
            int row = s_row + i * 8;
            __half2 h0 = __floats2half2_rn(pf[i*2].x,   pf[i*2].y);
            __half2 h1 = __floats2half2_rn(pf[i*2].z,   pf[i*2].w);
            __half2 h2 = __floats2half2_rn(pf[i*2+1].x, pf[i*2+1].y);
            __half2 h3 = __floats2half2_rn(pf[i*2+1].z, pf[i*2+1].w);
            uint4 pk;
            pk.x = *(uint32_t*)&h0; pk.y = *(uint32_t*)&h1;
            pk.z = *(uint32_t*)&h2; pk.w = *(uint32_t*)&h3;
            uint32_t off = (uint32_t)(row * 512 + ((s_cu ^ (row & 7)) << 4));
            *(uint4*)(smem + bufo + off) = pk;
        }
        if (tile == 0) CP_ASYNC_WAIT0();
        __syncthreads();                                    // S1

        if (tile < 15) {
            const float* nb = encb + (size_t)((tile + 1) * 32) * Dsz;
            #pragma unroll
            for (int i = 0; i < 4; i++) {
                const float* src = nb + (size_t)(s_row + i * 8) * Dsz + s_cu * 8;
                pf[i * 2]     = *(const float4*)(src);
                pf[i * 2 + 1] = *(const float4*)(src + 4);
            }
        }

        float acc[2][2][4];
        #pragma unroll
        for (int mt = 0; mt < 2; mt++)
            #pragma unroll
            for (int nt = 0; nt < 2; nt++)
                #pragma unroll
                for (int i = 0; i < 4; i++) acc[mt][nt][i] = 0.f;

        #pragma unroll
        for (int ks = 0; ks < 16; ks++) {
            int cuk = ks * 2 + (lane >> 4);
            uint32_t ah[2][4];
            #pragma unroll
            for (int mt = 0; mt < 2; mt++) {
                int row = mt * 16 + (lane & 15);
                uint32_t off = (uint32_t)(row * 512 + ((cuk ^ (row & 7)) << 4));
                ldmat4(ah[mt], sbase + bufo + off);
            }
            int brow = w * 16 + (lane & 15);
            uint32_t boff = (uint32_t)(brow * 512 + ((cuk ^ (brow & 7)) << 4));
            uint32_t rb[4];
            ldmat4(rb, sbase + SB_OFF + boff);
            #pragma unroll
            for (int mt = 0; mt < 2; mt++) {
                mma_f16(acc[mt][0], ah[mt], rb[0], rb[2]);
                mma_f16(acc[mt][1], ah[mt], rb[1], rb[3]);
            }
        }

        float part[4];
        #pragma unroll
        for (int mt = 0; mt < 2; mt++)
            #pragma unroll
            for (int half = 0; half < 2; half++) {
                float p = 0.f;
                #pragma unroll
                for (int nt = 0; nt < 2; nt++)
                    #pragma unroll
                    for (int j = 0; j < 2; j++) {
                        int h = w * 16 + nt * 8 + (lane & 3) * 2 + j;
                        float e = acc[mt][nt][half * 2 + j] + qs[h];
                        p += vs[h] * tanh_hw(e);
                    }
                part[mt * 2 + half] = p;
            }
        #pragma unroll
        for (int k = 0; k < 4; k++) {
            part[k] += __shfl_xor_sync(0xffffffffu, part[k], 1);
            part[k] += __shfl_xor_sync(0xffffffffu, part[k], 2);
        }
        if ((lane & 3) == 0) {
            #pragma unroll
            for (int mt = 0; mt < 2; mt++)
                #pragma unroll
                for (int half = 0; half < 2; half++) {
                    int row = mt * 16 + half * 8 + (lane >> 2);
                    sred[w][row] = part[mt * 2 + half];
                }
        }
        __syncthreads();                                    // S2

        if (t < 32) {
            float s = sred[0][t] + sred[1][t] + sred[2][t] + sred[3][t]
                    + sred[4][t] + sred[5][t] + sred[6][t] + sred[7][t];
            float e = __expf(s);
            e_w[t] = e;
            e_all[tile * 32 + t] = e;
            Zloc += e;
        }
        __syncthreads();                                    // S3

        if (t < 128) {
            int cu = t >> 2, byo = (4 * t) & 15;
            float2 cacc = make_float2(0.f, 0.f);
            #pragma unroll 8
            for (int l = 0; l < 32; l++) {
                uint32_t off = (uint32_t)(l * 512 + ((cu ^ (l & 7)) << 4) + byo);
                __half2 hv = *(const __half2*)(smem + bufo + off);
                float2 fv = __half22float2(hv);
                float e = e_w[l];
                cacc.x += e * fv.x;
                cacc.y += e * fv.y;
            }
            ctx.x += cacc.x;
            ctx.y += cacc.y;
        }
    }

    __syncthreads();
    if (t < 32) {
        float z = Zloc;
        #pragma unroll
        for (int o = 16; o > 0; o >>= 1)
            z += __shfl_xor_sync(0xffffffffu, z, o);
        if (lane == 0) sm_invZ = 1.f / z;
    }
    __syncthreads();

    float invZ = sm_invZ;
    if (t < 128) {
        x0_out[(size_t)b * X0W + Esz + 2 * t]     = ctx.x * invZ;
        x0_out[(size_t)b * X0W + Esz + 2 * t + 1] = ctx.y * invZ;
    }
    attnw_out[(size_t)b * Lsz + t]       = e_all[t]       * invZ;
    attnw_out[(size_t)b * Lsz + t + 256] = e_all[t + 256] * invZ;
}

// ---------------------------------------------------------------------------
__global__ void gru_kernel(const float* __restrict__ hprev, float* __restrict__ hnew,
                           const float* __restrict__ gi, const float* __restrict__ gh) {
    int b = blockIdx.x, h = threadIdx.x;
    int base = b * 3 * Hsz;
    float r = 1.f / (1.f + __expf(-(gi[base + h]       + gh[base + h])));
    float z = 1.f / (1.f + __expf(-(gi[base + Hsz + h] + gh[base + Hsz + h])));
    float n = tanhf(gi[base + 2 * Hsz + h] + r * gh[base + 2 * Hsz + h]);
    hnew[b * Hsz + h] = (1.f - z) * n + z * hprev[b * Hsz + h];
}

// ===========================================================================
extern "C" void kernel_launch(void* const* d_in, const int* in_sizes, int n_in,
                              void* d_out, int out_size)
{
    const float* embed  = (const float*)d_in[0];
    const float* hidden = (const float*)d_in[1];
    const float* enc    = (const float*)d_in[2];
    const float* Wq     = (const float*)d_in[3];
    const float* Wk     = (const float*)d_in[4];
    const float* av     = (const float*)d_in[5];
    const float* Wih0   = (const float*)d_in[6];
    const float* Whh0   = (const float*)d_in[7];
    const float* bih0   = (const float*)d_in[8];
    const float* bhh0   = (const float*)d_in[9];
    const float* Wih1   = (const float*)d_in[10];
    const float* Whh1   = (const float*)d_in[11];
    const float* bih1   = (const float*)d_in[12];
    const float* bhh1   = (const float*)d_in[13];
    const float* Wout   = (const float*)d_in[14];
    const float* bout   = (const float*)d_in[15];

    float* out_logits = (float*)d_out;
    float* out_hidden = out_logits + (size_t)Bsz * Vsz;
    float* out_attnw  = out_hidden + (size_t)2 * Bsz * Hsz;

    float *p_qproj, *p_x0, *p_gi, *p_gh, *p_gh2;
    cudaGetSymbolAddress((void**)&p_qproj, g_qproj);
    cudaGetSymbolAddress((void**)&p_x0,    g_x0);
    cudaGetSymbolAddress((void**)&p_gi,    g_gi);
    cudaGetSymbolAddress((void**)&p_gh,    g_gh);
    cudaGetSymbolAddress((void**)&p_gh2,   g_gh2);

    __nv_bfloat16 *wqH, *wqL, *wih0H, *wih0L, *whh0H, *whh0L,
                  *wih1H, *wih1L, *whh1H, *whh1L, *woutH, *woutL;
    cudaGetSymbolAddress((void**)&wqH,   g_wqH);   cudaGetSymbolAddress((void**)&wqL,   g_wqL);
    cudaGetSymbolAddress((void**)&wih0H, g_wih0H); cudaGetSymbolAddress((void**)&wih0L, g_wih0L);
    cudaGetSymbolAddress((void**)&whh0H, g_whh0H); cudaGetSymbolAddress((void**)&whh0L, g_whh0L);
    cudaGetSymbolAddress((void**)&wih1H, g_wih1H); cudaGetSymbolAddress((void**)&wih1L, g_wih1L);
    cudaGetSymbolAddress((void**)&whh1H, g_whh1H); cudaGetSymbolAddress((void**)&whh1L, g_whh1L);
    cudaGetSymbolAddress((void**)&woutH, g_woutH); cudaGetSymbolAddress((void**)&woutL, g_woutL);

    cudaFuncSetAttribute(fused_attn_kernel,
                         cudaFuncAttributeMaxDynamicSharedMemorySize, FS_SMEM);
    cudaFuncSetAttribute(mma_gemm64_kernel,
                         cudaFuncAttributeMaxDynamicSharedMemorySize, G_SMEM);

    const float* h0_prev = hidden;
    const float* h1_prev = hidden + (size_t)Bsz * Hsz;
    float* h0_new = out_hidden;
    float* h1_new = out_hidden + (size_t)Bsz * Hsz;

    // 1) prep
    prep_kernel<<<(OT + 255) / 256, 256>>>(Wq, Wih0, Whh0, Wih1, Whh1, Wout, Wk, embed);

    // 2) qproj (32 blocks)
    GJob jq  = { h1_prev, wqH, wqL, nullptr, p_qproj, Hsz, 2, Hsz };
    mma_gemm64_kernel<<<dim3(1, 32, 1), 256, G_SMEM>>>(jq, jq, jq);

    // 3) fused attention (R13 version)
    fused_attn_kernel<<<Bsz, 256, FS_SMEM>>>(enc, av, out_attnw, p_x0);

    // 4) batched: gi0, gh0, gh1 (288 blocks)
    GJob ja = { p_x0,    wih0H, wih0L, bih0, p_gi,  X0W, 5, 384 };
    GJob jb = { h0_prev, whh0H, whh0L, bhh0, p_gh,  Hsz, 2, 384 };
    GJob jc = { h1_prev, whh1H, whh1L, bhh1, p_gh2, Hsz, 2, 384 };
    mma_gemm64_kernel<<<dim3(3, 32, 3), 256, G_SMEM>>>(ja, jb, jc);

    // 5) gru0
    gru_kernel<<<Bsz, Hsz>>>(h0_prev, h0_new, p_gi, p_gh);

    // 6) gi1 (96 blocks)
    GJob jd = { h0_new, wih1H, wih1L, bih1, p_gi, Hsz, 2, 384 };
    mma_gemm64_kernel<<<dim3(3, 32, 1), 256, G_SMEM>>>(jd, jd, jd);

    // 7) gru1
    gru_kernel<<<Bsz, Hsz>>>(h1_prev, h1_new, p_gi, p_gh2);

    // 8) logits (256 blocks)
    GJob jl = { h1_new, woutH, woutL, bout, out_logits, Hsz, 2, Vsz };
    mma_gemm64_kernel<<<dim3(8, 32, 1), 256, G_SMEM>>>(jl, jl, jl);
}